// round 8
// baseline (speedup 1.0000x reference)
#include <cuda_runtime.h>
#include <cuda_bf16.h>
#include <math.h>
#include <cstdint>

// Problem constants
#define B_    4
#define T_    2048
#define DM    1024
#define NH    16
#define DH    64
#define ROWS  (B_ * T_)          // 8192
#define QKV_N (3 * DM)           // 3072

// Scratch (device globals: allocation-free)
__device__ float g_qkv[ROWS * QKV_N];      // [8192, 3072]  (tf32-rounded values)
__device__ float g_attn[ROWS * DM];        // [8192, 1024]  (tf32-rounded values)
__device__ float g_xr[ROWS * DM];          // rounded x
__device__ float g_wqkvT[QKV_N * DM];      // rounded w_qkv^T  [3072,1024]
__device__ float g_wprojT[DM * DM];        // rounded w_proj^T [1024,1024]

// ===========================================================================
// helpers
// ===========================================================================
__device__ __forceinline__ uint32_t smem_u32(const void* p) {
    uint32_t a;
    asm("{ .reg .u64 t; cvta.to.shared.u64 t, %1; cvt.u32.u64 %0, t; }"
        : "=r"(a) : "l"(p));
    return a;
}
__device__ __forceinline__ uint32_t f2tf32(float v) {
    uint32_t u;
    asm("cvt.rna.tf32.f32 %0, %1;" : "=r"(u) : "f"(v));
    return u;
}
__device__ __forceinline__ float roundtf(float v) {
    return __uint_as_float(f2tf32(v));
}
__device__ __forceinline__ uint32_t lds1(uint32_t a) {
    uint32_t v;
    asm volatile("ld.shared.b32 %0, [%1];" : "=r"(v) : "r"(a));
    return v;
}
__device__ __forceinline__ void mma_tf32(float* d, const uint32_t* a, const uint32_t* b) {
    asm volatile(
        "mma.sync.aligned.m16n8k8.row.col.f32.tf32.tf32.f32 "
        "{%0,%1,%2,%3}, {%4,%5,%6,%7}, {%8,%9}, {%0,%1,%2,%3};"
        : "+f"(d[0]), "+f"(d[1]), "+f"(d[2]), "+f"(d[3])
        : "r"(a[0]), "r"(a[1]), "r"(a[2]), "r"(a[3]), "r"(b[0]), "r"(b[1]));
}
__device__ __forceinline__ void cp_async16(uint32_t dst, const void* src) {
    asm volatile("cp.async.cg.shared.global [%0], [%1], 16;"
                 :: "r"(dst), "l"(src) : "memory");
}
#define CP_COMMIT() asm volatile("cp.async.commit_group;" ::: "memory")
#define CP_WAIT1()  asm volatile("cp.async.wait_group 1;" ::: "memory")

// ===========================================================================
// Pre-pass kernels
// ===========================================================================
__global__ __launch_bounds__(256) void round4_kernel(
    const float* __restrict__ in, float* __restrict__ out, int n4)
{
    int i = blockIdx.x * 256 + threadIdx.x;
    if (i < n4) {
        float4 v = ((const float4*)in)[i];
        v.x = roundtf(v.x); v.y = roundtf(v.y);
        v.z = roundtf(v.z); v.w = roundtf(v.w);
        ((float4*)out)[i] = v;
    }
}

// in: [R, C] row-major -> out: [C, R] row-major, values tf32-rounded.
__global__ __launch_bounds__(256) void transpose_round_kernel(
    const float* __restrict__ in, float* __restrict__ out, int R, int C)
{
    __shared__ float t[32][33];
    int cx = blockIdx.x * 32;
    int ry = blockIdx.y * 32;
#pragma unroll
    for (int i = 0; i < 32; i += 8)
        t[threadIdx.y + i][threadIdx.x] =
            in[(size_t)(ry + threadIdx.y + i) * C + cx + threadIdx.x];
    __syncthreads();
#pragma unroll
    for (int i = 0; i < 32; i += 8)
        out[(size_t)(cx + threadIdx.y + i) * R + ry + threadIdx.x] =
            roundtf(t[threadIdx.x][threadIdx.y + i]);
}

// ===========================================================================
// GEMM (NT): C[M,N] = A[M,K] @ BT[N,K]^T. All inputs pre-rounded to tf32.
// 3-stage cp.async ring, CTA 128x128, BK=32, 256 threads, 2 CTAs/SM.
// ===========================================================================
#define GEMM_SMEM (3 * 32768)

template<bool ROUND_OUT>
__global__ __launch_bounds__(256, 2) void gemm_cp_kernel(
    const float* __restrict__ A, const float* __restrict__ BT,
    float* __restrict__ C, int N, int K)
{
    extern __shared__ float gs[];
    const int tid  = threadIdx.x;
    const int lane = tid & 31;
    const int wid  = tid >> 5;
    const int wm   = wid >> 2;
    const int wn   = wid & 3;
    const int tig  = lane & 3;
    const int grp  = lane >> 2;
    const int bm = blockIdx.y * 128;
    const int bn = blockIdx.x * 128;
    const uint32_t sbase = smem_u32(gs);

    float acc[4][4][4];
#pragma unroll
    for (int i = 0; i < 4; ++i)
#pragma unroll
        for (int j = 0; j < 4; ++j)
#pragma unroll
            for (int r = 0; r < 4; ++r) acc[i][j][r] = 0.f;

    auto issue = [&](int c) {
        int s = c % 3;
        uint32_t abase = sbase + s * 32768;
        uint32_t bbase = abase + 16384;
        const float* Ap = A + (size_t)bm * K + c * 32;
        const float* Bp = BT + (size_t)bn * K + c * 32;
#pragma unroll
        for (int i = 0; i < 4; ++i) {
            int idx = tid + i * 256;
            int row = idx >> 3;
            int u   = idx & 7;
            uint32_t off = row * 128 + ((u ^ (row & 7)) * 16);
            cp_async16(abase + off, Ap + (size_t)row * K + u * 4);
            cp_async16(bbase + off, Bp + (size_t)row * K + u * 4);
        }
        CP_COMMIT();
    };

    const int NCH = K / 32;
    issue(0);
    issue(1);

    for (int c = 0; c < NCH; ++c) {
        CP_WAIT1();
        __syncthreads();
        if (c + 2 < NCH) issue(c + 2);

        const int s = c % 3;
        const uint32_t abase = sbase + s * 32768;
        const uint32_t bbase = abase + 16384;
#pragma unroll
        for (int g = 0; g < 4; ++g) {
            const uint32_t u0 = (uint32_t)(((2 * g)     ^ grp) * 16 + tig * 4);
            const uint32_t u1 = (uint32_t)(((2 * g + 1) ^ grp) * 16 + tig * 4);
            uint32_t af[4][4];
#pragma unroll
            for (int mt = 0; mt < 4; ++mt) {
                uint32_t rb = abase + (wm * 64 + mt * 16 + grp) * 128;
                af[mt][0] = lds1(rb + u0);
                af[mt][2] = lds1(rb + u1);
                af[mt][1] = lds1(rb + 1024 + u0);
                af[mt][3] = lds1(rb + 1024 + u1);
            }
#pragma unroll
            for (int nt = 0; nt < 4; ++nt) {
                uint32_t nb = bbase + (wn * 32 + nt * 8 + grp) * 128;
                uint32_t bf[2];
                bf[0] = lds1(nb + u0);
                bf[1] = lds1(nb + u1);
#pragma unroll
                for (int mt = 0; mt < 4; ++mt)
                    mma_tf32(acc[mt][nt], af[mt], bf);
            }
        }
    }

#pragma unroll
    for (int mt = 0; mt < 4; ++mt) {
        int r = bm + wm * 64 + mt * 16 + grp;
#pragma unroll
        for (int nt = 0; nt < 4; ++nt) {
            int cc = bn + wn * 32 + nt * 8 + 2 * tig;
            float2 v0, v1;
            if (ROUND_OUT) {
                v0 = make_float2(roundtf(acc[mt][nt][0]), roundtf(acc[mt][nt][1]));
                v1 = make_float2(roundtf(acc[mt][nt][2]), roundtf(acc[mt][nt][3]));
            } else {
                v0 = make_float2(acc[mt][nt][0], acc[mt][nt][1]);
                v1 = make_float2(acc[mt][nt][2], acc[mt][nt][3]);
            }
            *(float2*)(C + (size_t)r * N + cc)       = v0;
            *(float2*)(C + (size_t)(r + 8) * N + cc) = v1;
        }
    }
}

// ===========================================================================
// Flash attention (tf32 mma.sync). Triple-buffered K/V (ONE barrier per
// tile), early cp.async issue, exp2-domain softmax (log2e folded into Q).
// Grid: (T/128, B*NH). Block 256 (8 warps). Warp w owns Q rows [16w,16w+16).
// smem: Ps[128][68] (Q staging + P), Ks[3][64][68], Vs[3][64][68].
// ===========================================================================
#define FSTR 68
#define KVT  (64 * FSTR)
#define FLASH_SMEM ((128 * FSTR + 6 * KVT) * 4)

__global__ __launch_bounds__(256) void flash_mma_kernel(
    const float* __restrict__ qkv, float* __restrict__ attn)
{
    extern __shared__ float sm[];
    float* Ps  = sm;                        // 128 x FSTR
    float* KsA = sm + 128 * FSTR;           // 3 x 64 x FSTR
    float* VsA = KsA + 3 * KVT;             // 3 x 64 x FSTR

    const int tid  = threadIdx.x;
    const int lane = tid & 31;
    const int wid  = tid >> 5;
    const int grp  = lane >> 2;
    const int tig  = lane & 3;
    const int qt = blockIdx.x;
    const int bh = blockIdx.y;
    const int b  = bh >> 4;
    const int h  = bh & 15;

    const int r0 = wid * 16 + grp;

    auto issue_kv = [&](int j) {
        int s = j % 3;
        float* Kd = KsA + s * KVT;
        float* Vd = VsA + s * KVT;
        const size_t kbase = (size_t)(b * T_ + j * 64) * QKV_N + h * DH;
#pragma unroll
        for (int i = 0; i < 4; ++i) {
            int idx = tid + i * 256;
            int row = idx >> 4;
            int c4  = idx & 15;
            const float* gk = qkv + kbase + (size_t)row * QKV_N + c4 * 4 + DM;
            cp_async16(smem_u32(&Kd[row * FSTR + c4 * 4]), gk);
            cp_async16(smem_u32(&Vd[row * FSTR + c4 * 4]), gk + DM);
        }
        CP_COMMIT();
    };

    issue_kv(0);
    issue_kv(1);

    // ---- stage Q tile (x 0.125*log2e; values already tf32) ----
    const float QSCALE = 0.125f * 1.4426950408889634f;
    const size_t qbase = (size_t)(b * T_ + qt * 128) * QKV_N + h * DH;
#pragma unroll
    for (int i = 0; i < 8; ++i) {
        int idx = tid + i * 256;
        int row = idx >> 4;
        int c4  = idx & 15;
        float4 v = *(const float4*)&qkv[qbase + (size_t)row * QKV_N + c4 * 4];
        float* p = &Ps[row * FSTR + c4 * 4];
        p[0] = roundtf(v.x * QSCALE);
        p[1] = roundtf(v.y * QSCALE);
        p[2] = roundtf(v.z * QSCALE);
        p[3] = roundtf(v.w * QSCALE);
    }
    __syncthreads();

    // ---- Q fragments into registers ----
    uint32_t qf[8][4];
#pragma unroll
    for (int kc = 0; kc < 8; ++kc) {
        qf[kc][0] = __float_as_uint(Ps[r0 * FSTR + 8 * kc + tig]);
        qf[kc][1] = __float_as_uint(Ps[(r0 + 8) * FSTR + 8 * kc + tig]);
        qf[kc][2] = __float_as_uint(Ps[r0 * FSTR + 8 * kc + tig + 4]);
        qf[kc][3] = __float_as_uint(Ps[(r0 + 8) * FSTR + 8 * kc + tig + 4]);
    }

    float Oa[8][4];
#pragma unroll
    for (int nt = 0; nt < 8; ++nt)
#pragma unroll
        for (int r = 0; r < 4; ++r) Oa[nt][r] = 0.f;
    float mrun0 = -INFINITY, mrun1 = -INFINITY;
    float lrun0 = 0.f, lrun1 = 0.f;

    const int NT = T_ / 64;
    for (int j = 0; j < NT; ++j) {
        CP_WAIT1();
        __syncthreads();             // sole barrier: tile j resident, all warps
                                     // done with iteration j-1 (3-buffer safety)
        if (j + 2 < NT) issue_kv(j + 2);

        const float* Kb = KsA + (j % 3) * KVT;
        const float* Vb = VsA + (j % 3) * KVT;

        // ---- S = Q @ K^T (log2 domain) ----
        float Sa[8][4];
#pragma unroll
        for (int nt = 0; nt < 8; ++nt)
#pragma unroll
            for (int r = 0; r < 4; ++r) Sa[nt][r] = 0.f;
#pragma unroll
        for (int kc = 0; kc < 8; ++kc) {
#pragma unroll
            for (int nt = 0; nt < 8; ++nt) {
                uint32_t bf[2];
                bf[0] = __float_as_uint(Kb[(8 * nt + grp) * FSTR + 8 * kc + tig]);
                bf[1] = __float_as_uint(Kb[(8 * nt + grp) * FSTR + 8 * kc + tig + 4]);
                mma_tf32(Sa[nt], qf[kc], bf);
            }
        }

        // ---- online softmax (exp2) ----
        float ml0 = -INFINITY, ml1 = -INFINITY;
#pragma unroll
        for (int nt = 0; nt < 8; ++nt) {
            ml0 = fmaxf(ml0, fmaxf(Sa[nt][0], Sa[nt][1]));
            ml1 = fmaxf(ml1, fmaxf(Sa[nt][2], Sa[nt][3]));
        }
        ml0 = fmaxf(ml0, __shfl_xor_sync(0xffffffffu, ml0, 1));
        ml0 = fmaxf(ml0, __shfl_xor_sync(0xffffffffu, ml0, 2));
        ml1 = fmaxf(ml1, __shfl_xor_sync(0xffffffffu, ml1, 1));
        ml1 = fmaxf(ml1, __shfl_xor_sync(0xffffffffu, ml1, 2));

        float mnew0 = fmaxf(mrun0, ml0);
        float mnew1 = fmaxf(mrun1, ml1);
        float corr0 = exp2f(mrun0 - mnew0);
        float corr1 = exp2f(mrun1 - mnew1);

        float ls0 = 0.f, ls1 = 0.f;
#pragma unroll
        for (int nt = 0; nt < 8; ++nt) {
            float p00 = exp2f(Sa[nt][0] - mnew0);
            float p01 = exp2f(Sa[nt][1] - mnew0);
            float p10 = exp2f(Sa[nt][2] - mnew1);
            float p11 = exp2f(Sa[nt][3] - mnew1);
            ls0 += p00 + p01;
            ls1 += p10 + p11;
            float2 w0, w1;
            w0.x = __uint_as_float(f2tf32(p00));
            w0.y = __uint_as_float(f2tf32(p01));
            w1.x = __uint_as_float(f2tf32(p10));
            w1.y = __uint_as_float(f2tf32(p11));
            *(float2*)&Ps[r0 * FSTR + 8 * nt + 2 * tig]       = w0;
            *(float2*)&Ps[(r0 + 8) * FSTR + 8 * nt + 2 * tig] = w1;
        }
        ls0 += __shfl_xor_sync(0xffffffffu, ls0, 1);
        ls0 += __shfl_xor_sync(0xffffffffu, ls0, 2);
        ls1 += __shfl_xor_sync(0xffffffffu, ls1, 1);
        ls1 += __shfl_xor_sync(0xffffffffu, ls1, 2);

        lrun0 = lrun0 * corr0 + ls0;
        lrun1 = lrun1 * corr1 + ls1;
        mrun0 = mnew0;
        mrun1 = mnew1;
#pragma unroll
        for (int nt = 0; nt < 8; ++nt) {
            Oa[nt][0] *= corr0;
            Oa[nt][1] *= corr0;
            Oa[nt][2] *= corr1;
            Oa[nt][3] *= corr1;
        }
        __syncwarp();

        // ---- O += P @ V ----
#pragma unroll
        for (int kc = 0; kc < 8; ++kc) {
            uint32_t af[4];
            af[0] = __float_as_uint(Ps[r0 * FSTR + 8 * kc + tig]);
            af[1] = __float_as_uint(Ps[(r0 + 8) * FSTR + 8 * kc + tig]);
            af[2] = __float_as_uint(Ps[r0 * FSTR + 8 * kc + tig + 4]);
            af[3] = __float_as_uint(Ps[(r0 + 8) * FSTR + 8 * kc + tig + 4]);
#pragma unroll
            for (int nt = 0; nt < 8; ++nt) {
                uint32_t bf[2];
                bf[0] = __float_as_uint(Vb[(8 * kc + tig) * FSTR + 8 * nt + grp]);
                bf[1] = __float_as_uint(Vb[(8 * kc + tig + 4) * FSTR + 8 * nt + grp]);
                mma_tf32(Oa[nt], af, bf);
            }
        }
        // no bottom barrier: top-of-loop __syncthreads + 3 buffers make it safe
    }

    // ---- epilogue (rounded: proj GEMM consumes raw bits) ----
    const float inv0 = 1.f / lrun0;
    const float inv1 = 1.f / lrun1;
    float* o0 = attn + (size_t)(b * T_ + qt * 128 + r0) * DM + h * DH;
    float* o1 = attn + (size_t)(b * T_ + qt * 128 + r0 + 8) * DM + h * DH;
#pragma unroll
    for (int nt = 0; nt < 8; ++nt) {
        float2 v0 = make_float2(roundtf(Oa[nt][0] * inv0), roundtf(Oa[nt][1] * inv0));
        float2 v1 = make_float2(roundtf(Oa[nt][2] * inv1), roundtf(Oa[nt][3] * inv1));
        *(float2*)(o0 + 8 * nt + 2 * tig) = v0;
        *(float2*)(o1 + 8 * nt + 2 * tig) = v1;
    }
}

// ---------------------------------------------------------------------------
extern "C" void kernel_launch(void* const* d_in, const int* in_sizes, int n_in,
                              void* d_out, int out_size)
{
    const float* x      = (const float*)d_in[0];   // [4,2048,1024]
    const float* w_qkv  = (const float*)d_in[1];   // [1024,3072]
    const float* w_proj = (const float*)d_in[2];   // [1024,1024]
    float* out = (float*)d_out;                    // [4,2048,1024]

    float *qkvbuf, *attnbuf, *xr, *wqkvT, *wprojT;
    cudaGetSymbolAddress((void**)&qkvbuf, g_qkv);
    cudaGetSymbolAddress((void**)&attnbuf, g_attn);
    cudaGetSymbolAddress((void**)&xr, g_xr);
    cudaGetSymbolAddress((void**)&wqkvT, g_wqkvT);
    cudaGetSymbolAddress((void**)&wprojT, g_wprojT);

    static bool attr_set = false;
    if (!attr_set) {
        cudaFuncSetAttribute(flash_mma_kernel,
                             cudaFuncAttributeMaxDynamicSharedMemorySize,
                             FLASH_SMEM);
        cudaFuncSetAttribute(gemm_cp_kernel<true>,
                             cudaFuncAttributeMaxDynamicSharedMemorySize,
                             GEMM_SMEM);
        cudaFuncSetAttribute(gemm_cp_kernel<false>,
                             cudaFuncAttributeMaxDynamicSharedMemorySize,
                             GEMM_SMEM);
        attr_set = true;
    }

    // 0) Pre-pass: round x; transpose+round weights.
    {
        int n4 = ROWS * DM / 4;
        round4_kernel<<<(n4 + 255) / 256, 256>>>(x, xr, n4);
        dim3 tb(32, 8);
        transpose_round_kernel<<<dim3(QKV_N / 32, DM / 32), tb>>>(w_qkv, wqkvT, DM, QKV_N);
        transpose_round_kernel<<<dim3(DM / 32, DM / 32), tb>>>(w_proj, wprojT, DM, DM);
    }

    // 1) QKV projection: [8192,1024] @ [1024,3072] -> rounded qkv
    {
        dim3 grid(QKV_N / 128, ROWS / 128);
        gemm_cp_kernel<true><<<grid, 256, GEMM_SMEM>>>(xr, wqkvT, qkvbuf, QKV_N, DM);
    }

    // 2) Attention -> rounded attn
    {
        dim3 grid(T_ / 128, B_ * NH);
        flash_mma_kernel<<<grid, 256, FLASH_SMEM>>>(qkvbuf, attnbuf);
    }

    // 3) Output projection: [8192,1024] @ [1024,1024] -> fp32 out
    {
        dim3 grid(DM / 128, ROWS / 128);
        gemm_cp_kernel<false><<<grid, 256, GEMM_SMEM>>>(attnbuf, wprojT, out, DM, DM);
    }
}

// round 9
// speedup vs baseline: 1.5542x; 1.5542x over previous
#include <cuda_runtime.h>
#include <cuda_bf16.h>
#include <math.h>
#include <cstdint>

// Problem constants
#define B_    4
#define T_    2048
#define DM    1024
#define NH    16
#define DH    64
#define ROWS  (B_ * T_)          // 8192
#define QKV_N (3 * DM)           // 3072

// Scratch (device globals: allocation-free)
__device__ float g_qkv[ROWS * QKV_N];      // [8192, 3072]  (tf32-rounded values)
__device__ float g_attn[ROWS * DM];        // [8192, 1024]  (tf32-rounded values)
__device__ float g_xr[ROWS * DM];          // rounded x
__device__ float g_wqkvT[QKV_N * DM];      // rounded w_qkv^T  [3072,1024]
__device__ float g_wprojT[DM * DM];        // rounded w_proj^T [1024,1024]

// ===========================================================================
// helpers
// ===========================================================================
__device__ __forceinline__ uint32_t smem_u32(const void* p) {
    uint32_t a;
    asm("{ .reg .u64 t; cvta.to.shared.u64 t, %1; cvt.u32.u64 %0, t; }"
        : "=r"(a) : "l"(p));
    return a;
}
__device__ __forceinline__ uint32_t f2tf32(float v) {
    uint32_t u;
    asm("cvt.rna.tf32.f32 %0, %1;" : "=r"(u) : "f"(v));
    return u;
}
__device__ __forceinline__ float roundtf(float v) {
    return __uint_as_float(f2tf32(v));
}
// single-MUFU exp2 (no libdevice fixups, flag-independent)
__device__ __forceinline__ float ex2(float v) {
    float r;
    asm("ex2.approx.ftz.f32 %0, %1;" : "=f"(r) : "f"(v));
    return r;
}
__device__ __forceinline__ uint32_t lds1(uint32_t a) {
    uint32_t v;
    asm volatile("ld.shared.b32 %0, [%1];" : "=r"(v) : "r"(a));
    return v;
}
__device__ __forceinline__ void mma_tf32(float* d, const uint32_t* a, const uint32_t* b) {
    asm volatile(
        "mma.sync.aligned.m16n8k8.row.col.f32.tf32.tf32.f32 "
        "{%0,%1,%2,%3}, {%4,%5,%6,%7}, {%8,%9}, {%0,%1,%2,%3};"
        : "+f"(d[0]), "+f"(d[1]), "+f"(d[2]), "+f"(d[3])
        : "r"(a[0]), "r"(a[1]), "r"(a[2]), "r"(a[3]), "r"(b[0]), "r"(b[1]));
}
__device__ __forceinline__ void cp_async16(uint32_t dst, const void* src) {
    asm volatile("cp.async.cg.shared.global [%0], [%1], 16;"
                 :: "r"(dst), "l"(src) : "memory");
}
#define CP_COMMIT() asm volatile("cp.async.commit_group;" ::: "memory")
#define CP_WAIT1()  asm volatile("cp.async.wait_group 1;" ::: "memory")

// ===========================================================================
// Pre-pass kernels
// ===========================================================================
__global__ __launch_bounds__(256) void round4_kernel(
    const float* __restrict__ in, float* __restrict__ out, int n4)
{
    int i = blockIdx.x * 256 + threadIdx.x;
    if (i < n4) {
        float4 v = ((const float4*)in)[i];
        v.x = roundtf(v.x); v.y = roundtf(v.y);
        v.z = roundtf(v.z); v.w = roundtf(v.w);
        ((float4*)out)[i] = v;
    }
}

// in: [R, C] row-major -> out: [C, R] row-major, values tf32-rounded.
__global__ __launch_bounds__(256) void transpose_round_kernel(
    const float* __restrict__ in, float* __restrict__ out, int R, int C)
{
    __shared__ float t[32][33];
    int cx = blockIdx.x * 32;
    int ry = blockIdx.y * 32;
#pragma unroll
    for (int i = 0; i < 32; i += 8)
        t[threadIdx.y + i][threadIdx.x] =
            in[(size_t)(ry + threadIdx.y + i) * C + cx + threadIdx.x];
    __syncthreads();
#pragma unroll
    for (int i = 0; i < 32; i += 8)
        out[(size_t)(cx + threadIdx.y + i) * R + ry + threadIdx.x] =
            roundtf(t[threadIdx.x][threadIdx.y + i]);
}

// ===========================================================================
// GEMM (NT): C[M,N] = A[M,K] @ BT[N,K]^T. All inputs pre-rounded to tf32.
// 3-stage cp.async ring, CTA 128x128, BK=32, 256 threads, 2 CTAs/SM.
// ===========================================================================
#define GEMM_SMEM (3 * 32768)

template<bool ROUND_OUT>
__global__ __launch_bounds__(256, 2) void gemm_cp_kernel(
    const float* __restrict__ A, const float* __restrict__ BT,
    float* __restrict__ C, int N, int K)
{
    extern __shared__ float gs[];
    const int tid  = threadIdx.x;
    const int lane = tid & 31;
    const int wid  = tid >> 5;
    const int wm   = wid >> 2;
    const int wn   = wid & 3;
    const int tig  = lane & 3;
    const int grp  = lane >> 2;
    const int bm = blockIdx.y * 128;
    const int bn = blockIdx.x * 128;
    const uint32_t sbase = smem_u32(gs);

    float acc[4][4][4];
#pragma unroll
    for (int i = 0; i < 4; ++i)
#pragma unroll
        for (int j = 0; j < 4; ++j)
#pragma unroll
            for (int r = 0; r < 4; ++r) acc[i][j][r] = 0.f;

    auto issue = [&](int c) {
        int s = c % 3;
        uint32_t abase = sbase + s * 32768;
        uint32_t bbase = abase + 16384;
        const float* Ap = A + (size_t)bm * K + c * 32;
        const float* Bp = BT + (size_t)bn * K + c * 32;
#pragma unroll
        for (int i = 0; i < 4; ++i) {
            int idx = tid + i * 256;
            int row = idx >> 3;
            int u   = idx & 7;
            uint32_t off = row * 128 + ((u ^ (row & 7)) * 16);
            cp_async16(abase + off, Ap + (size_t)row * K + u * 4);
            cp_async16(bbase + off, Bp + (size_t)row * K + u * 4);
        }
        CP_COMMIT();
    };

    const int NCH = K / 32;
    issue(0);
    issue(1);

    for (int c = 0; c < NCH; ++c) {
        CP_WAIT1();
        __syncthreads();
        if (c + 2 < NCH) issue(c + 2);

        const int s = c % 3;
        const uint32_t abase = sbase + s * 32768;
        const uint32_t bbase = abase + 16384;
#pragma unroll
        for (int g = 0; g < 4; ++g) {
            const uint32_t u0 = (uint32_t)(((2 * g)     ^ grp) * 16 + tig * 4);
            const uint32_t u1 = (uint32_t)(((2 * g + 1) ^ grp) * 16 + tig * 4);
            uint32_t af[4][4];
#pragma unroll
            for (int mt = 0; mt < 4; ++mt) {
                uint32_t rb = abase + (wm * 64 + mt * 16 + grp) * 128;
                af[mt][0] = lds1(rb + u0);
                af[mt][2] = lds1(rb + u1);
                af[mt][1] = lds1(rb + 1024 + u0);
                af[mt][3] = lds1(rb + 1024 + u1);
            }
#pragma unroll
            for (int nt = 0; nt < 4; ++nt) {
                uint32_t nb = bbase + (wn * 32 + nt * 8 + grp) * 128;
                uint32_t bf[2];
                bf[0] = lds1(nb + u0);
                bf[1] = lds1(nb + u1);
#pragma unroll
                for (int mt = 0; mt < 4; ++mt)
                    mma_tf32(acc[mt][nt], af[mt], bf);
            }
        }
    }

#pragma unroll
    for (int mt = 0; mt < 4; ++mt) {
        int r = bm + wm * 64 + mt * 16 + grp;
#pragma unroll
        for (int nt = 0; nt < 4; ++nt) {
            int cc = bn + wn * 32 + nt * 8 + 2 * tig;
            float2 v0, v1;
            if (ROUND_OUT) {
                v0 = make_float2(roundtf(acc[mt][nt][0]), roundtf(acc[mt][nt][1]));
                v1 = make_float2(roundtf(acc[mt][nt][2]), roundtf(acc[mt][nt][3]));
            } else {
                v0 = make_float2(acc[mt][nt][0], acc[mt][nt][1]);
                v1 = make_float2(acc[mt][nt][2], acc[mt][nt][3]);
            }
            *(float2*)(C + (size_t)r * N + cc)       = v0;
            *(float2*)(C + (size_t)(r + 8) * N + cc) = v1;
        }
    }
}

// ===========================================================================
// Flash attention (tf32 mma.sync). Triple-buffered K/V (ONE barrier per
// tile), early cp.async issue, exp2-domain softmax via raw MUFU ex2.approx.
// Grid: (T/128, B*NH). Block 256 (8 warps). Warp w owns Q rows [16w,16w+16).
// smem: Ps[128][68] (Q staging + P), Ks[3][64][68], Vs[3][64][68].
// ===========================================================================
#define FSTR 68
#define KVT  (64 * FSTR)
#define FLASH_SMEM ((128 * FSTR + 6 * KVT) * 4)

__global__ __launch_bounds__(256) void flash_mma_kernel(
    const float* __restrict__ qkv, float* __restrict__ attn)
{
    extern __shared__ float sm[];
    float* Ps  = sm;                        // 128 x FSTR
    float* KsA = sm + 128 * FSTR;           // 3 x 64 x FSTR
    float* VsA = KsA + 3 * KVT;             // 3 x 64 x FSTR

    const int tid  = threadIdx.x;
    const int lane = tid & 31;
    const int wid  = tid >> 5;
    const int grp  = lane >> 2;
    const int tig  = lane & 3;
    const int qt = blockIdx.x;
    const int bh = blockIdx.y;
    const int b  = bh >> 4;
    const int h  = bh & 15;

    const int r0 = wid * 16 + grp;

    auto issue_kv = [&](int j) {
        int s = j % 3;
        float* Kd = KsA + s * KVT;
        float* Vd = VsA + s * KVT;
        const size_t kbase = (size_t)(b * T_ + j * 64) * QKV_N + h * DH;
#pragma unroll
        for (int i = 0; i < 4; ++i) {
            int idx = tid + i * 256;
            int row = idx >> 4;
            int c4  = idx & 15;
            const float* gk = qkv + kbase + (size_t)row * QKV_N + c4 * 4 + DM;
            cp_async16(smem_u32(&Kd[row * FSTR + c4 * 4]), gk);
            cp_async16(smem_u32(&Vd[row * FSTR + c4 * 4]), gk + DM);
        }
        CP_COMMIT();
    };

    issue_kv(0);
    issue_kv(1);

    // ---- stage Q tile (x 0.125*log2e; values already tf32) ----
    const float QSCALE = 0.125f * 1.4426950408889634f;
    const size_t qbase = (size_t)(b * T_ + qt * 128) * QKV_N + h * DH;
#pragma unroll
    for (int i = 0; i < 8; ++i) {
        int idx = tid + i * 256;
        int row = idx >> 4;
        int c4  = idx & 15;
        float4 v = *(const float4*)&qkv[qbase + (size_t)row * QKV_N + c4 * 4];
        float* p = &Ps[row * FSTR + c4 * 4];
        p[0] = roundtf(v.x * QSCALE);
        p[1] = roundtf(v.y * QSCALE);
        p[2] = roundtf(v.z * QSCALE);
        p[3] = roundtf(v.w * QSCALE);
    }
    __syncthreads();

    // ---- Q fragments into registers ----
    uint32_t qf[8][4];
#pragma unroll
    for (int kc = 0; kc < 8; ++kc) {
        qf[kc][0] = __float_as_uint(Ps[r0 * FSTR + 8 * kc + tig]);
        qf[kc][1] = __float_as_uint(Ps[(r0 + 8) * FSTR + 8 * kc + tig]);
        qf[kc][2] = __float_as_uint(Ps[r0 * FSTR + 8 * kc + tig + 4]);
        qf[kc][3] = __float_as_uint(Ps[(r0 + 8) * FSTR + 8 * kc + tig + 4]);
    }

    float Oa[8][4];
#pragma unroll
    for (int nt = 0; nt < 8; ++nt)
#pragma unroll
        for (int r = 0; r < 4; ++r) Oa[nt][r] = 0.f;
    float mrun0 = -INFINITY, mrun1 = -INFINITY;
    float lrun0 = 0.f, lrun1 = 0.f;

    const int NT = T_ / 64;
    for (int j = 0; j < NT; ++j) {
        CP_WAIT1();
        __syncthreads();             // sole barrier: tile j resident, all warps
                                     // done with iteration j-1 (3-buffer safety)
        if (j + 2 < NT) issue_kv(j + 2);

        const float* Kb = KsA + (j % 3) * KVT;
        const float* Vb = VsA + (j % 3) * KVT;

        // ---- S = Q @ K^T (log2 domain) ----
        float Sa[8][4];
#pragma unroll
        for (int nt = 0; nt < 8; ++nt)
#pragma unroll
            for (int r = 0; r < 4; ++r) Sa[nt][r] = 0.f;
#pragma unroll
        for (int kc = 0; kc < 8; ++kc) {
#pragma unroll
            for (int nt = 0; nt < 8; ++nt) {
                uint32_t bf[2];
                bf[0] = __float_as_uint(Kb[(8 * nt + grp) * FSTR + 8 * kc + tig]);
                bf[1] = __float_as_uint(Kb[(8 * nt + grp) * FSTR + 8 * kc + tig + 4]);
                mma_tf32(Sa[nt], qf[kc], bf);
            }
        }

        // ---- online softmax (MUFU ex2) ----
        float ml0 = -INFINITY, ml1 = -INFINITY;
#pragma unroll
        for (int nt = 0; nt < 8; ++nt) {
            ml0 = fmaxf(ml0, fmaxf(Sa[nt][0], Sa[nt][1]));
            ml1 = fmaxf(ml1, fmaxf(Sa[nt][2], Sa[nt][3]));
        }
        ml0 = fmaxf(ml0, __shfl_xor_sync(0xffffffffu, ml0, 1));
        ml0 = fmaxf(ml0, __shfl_xor_sync(0xffffffffu, ml0, 2));
        ml1 = fmaxf(ml1, __shfl_xor_sync(0xffffffffu, ml1, 1));
        ml1 = fmaxf(ml1, __shfl_xor_sync(0xffffffffu, ml1, 2));

        float mnew0 = fmaxf(mrun0, ml0);
        float mnew1 = fmaxf(mrun1, ml1);
        float corr0 = ex2(mrun0 - mnew0);
        float corr1 = ex2(mrun1 - mnew1);

        float ls0 = 0.f, ls1 = 0.f;
#pragma unroll
        for (int nt = 0; nt < 8; ++nt) {
            float p00 = ex2(Sa[nt][0] - mnew0);
            float p01 = ex2(Sa[nt][1] - mnew0);
            float p10 = ex2(Sa[nt][2] - mnew1);
            float p11 = ex2(Sa[nt][3] - mnew1);
            ls0 += p00 + p01;
            ls1 += p10 + p11;
            float2 w0, w1;
            w0.x = __uint_as_float(f2tf32(p00));
            w0.y = __uint_as_float(f2tf32(p01));
            w1.x = __uint_as_float(f2tf32(p10));
            w1.y = __uint_as_float(f2tf32(p11));
            *(float2*)&Ps[r0 * FSTR + 8 * nt + 2 * tig]       = w0;
            *(float2*)&Ps[(r0 + 8) * FSTR + 8 * nt + 2 * tig] = w1;
        }
        ls0 += __shfl_xor_sync(0xffffffffu, ls0, 1);
        ls0 += __shfl_xor_sync(0xffffffffu, ls0, 2);
        ls1 += __shfl_xor_sync(0xffffffffu, ls1, 1);
        ls1 += __shfl_xor_sync(0xffffffffu, ls1, 2);

        lrun0 = lrun0 * corr0 + ls0;
        lrun1 = lrun1 * corr1 + ls1;
        mrun0 = mnew0;
        mrun1 = mnew1;
#pragma unroll
        for (int nt = 0; nt < 8; ++nt) {
            Oa[nt][0] *= corr0;
            Oa[nt][1] *= corr0;
            Oa[nt][2] *= corr1;
            Oa[nt][3] *= corr1;
        }
        __syncwarp();

        // ---- O += P @ V ----
#pragma unroll
        for (int kc = 0; kc < 8; ++kc) {
            uint32_t af[4];
            af[0] = __float_as_uint(Ps[r0 * FSTR + 8 * kc + tig]);
            af[1] = __float_as_uint(Ps[(r0 + 8) * FSTR + 8 * kc + tig]);
            af[2] = __float_as_uint(Ps[r0 * FSTR + 8 * kc + tig + 4]);
            af[3] = __float_as_uint(Ps[(r0 + 8) * FSTR + 8 * kc + tig + 4]);
#pragma unroll
            for (int nt = 0; nt < 8; ++nt) {
                uint32_t bf[2];
                bf[0] = __float_as_uint(Vb[(8 * kc + tig) * FSTR + 8 * nt + grp]);
                bf[1] = __float_as_uint(Vb[(8 * kc + tig + 4) * FSTR + 8 * nt + grp]);
                mma_tf32(Oa[nt], af, bf);
            }
        }
        // no bottom barrier: top-of-loop __syncthreads + 3 buffers make it safe
    }

    // ---- epilogue (rounded: proj GEMM consumes raw bits) ----
    const float inv0 = 1.f / lrun0;
    const float inv1 = 1.f / lrun1;
    float* o0 = attn + (size_t)(b * T_ + qt * 128 + r0) * DM + h * DH;
    float* o1 = attn + (size_t)(b * T_ + qt * 128 + r0 + 8) * DM + h * DH;
#pragma unroll
    for (int nt = 0; nt < 8; ++nt) {
        float2 v0 = make_float2(roundtf(Oa[nt][0] * inv0), roundtf(Oa[nt][1] * inv0));
        float2 v1 = make_float2(roundtf(Oa[nt][2] * inv1), roundtf(Oa[nt][3] * inv1));
        *(float2*)(o0 + 8 * nt + 2 * tig) = v0;
        *(float2*)(o1 + 8 * nt + 2 * tig) = v1;
    }
}

// ---------------------------------------------------------------------------
extern "C" void kernel_launch(void* const* d_in, const int* in_sizes, int n_in,
                              void* d_out, int out_size)
{
    const float* x      = (const float*)d_in[0];   // [4,2048,1024]
    const float* w_qkv  = (const float*)d_in[1];   // [1024,3072]
    const float* w_proj = (const float*)d_in[2];   // [1024,1024]
    float* out = (float*)d_out;                    // [4,2048,1024]

    float *qkvbuf, *attnbuf, *xr, *wqkvT, *wprojT;
    cudaGetSymbolAddress((void**)&qkvbuf, g_qkv);
    cudaGetSymbolAddress((void**)&attnbuf, g_attn);
    cudaGetSymbolAddress((void**)&xr, g_xr);
    cudaGetSymbolAddress((void**)&wqkvT, g_wqkvT);
    cudaGetSymbolAddress((void**)&wprojT, g_wprojT);

    static bool attr_set = false;
    if (!attr_set) {
        cudaFuncSetAttribute(flash_mma_kernel,
                             cudaFuncAttributeMaxDynamicSharedMemorySize,
                             FLASH_SMEM);
        cudaFuncSetAttribute(gemm_cp_kernel<true>,
                             cudaFuncAttributeMaxDynamicSharedMemorySize,
                             GEMM_SMEM);
        cudaFuncSetAttribute(gemm_cp_kernel<false>,
                             cudaFuncAttributeMaxDynamicSharedMemorySize,
                             GEMM_SMEM);
        attr_set = true;
    }

    // 0) Pre-pass: round x; transpose+round weights.
    {
        int n4 = ROWS * DM / 4;
        round4_kernel<<<(n4 + 255) / 256, 256>>>(x, xr, n4);
        dim3 tb(32, 8);
        transpose_round_kernel<<<dim3(QKV_N / 32, DM / 32), tb>>>(w_qkv, wqkvT, DM, QKV_N);
        transpose_round_kernel<<<dim3(DM / 32, DM / 32), tb>>>(w_proj, wprojT, DM, DM);
    }

    // 1) QKV projection: [8192,1024] @ [1024,3072] -> rounded qkv
    {
        dim3 grid(QKV_N / 128, ROWS / 128);
        gemm_cp_kernel<true><<<grid, 256, GEMM_SMEM>>>(xr, wqkvT, qkvbuf, QKV_N, DM);
    }

    // 2) Attention -> rounded attn
    {
        dim3 grid(T_ / 128, B_ * NH);
        flash_mma_kernel<<<grid, 256, FLASH_SMEM>>>(qkvbuf, attnbuf);
    }

    // 3) Output projection: [8192,1024] @ [1024,1024] -> fp32 out
    {
        dim3 grid(DM / 128, ROWS / 128);
        gemm_cp_kernel<false><<<grid, 256, GEMM_SMEM>>>(attnbuf, wprojT, out, DM, DM);
    }
}

// round 10
// speedup vs baseline: 1.7362x; 1.1171x over previous
#include <cuda_runtime.h>
#include <cuda_bf16.h>
#include <math.h>
#include <cstdint>

// Problem constants
#define B_    4
#define T_    2048
#define DM    1024
#define NH    16
#define DH    64
#define ROWS  (B_ * T_)          // 8192
#define QKV_N (3 * DM)           // 3072

// Scratch (device globals: allocation-free)
__device__ float g_qkv[ROWS * QKV_N];      // [8192, 3072]  (tf32-rounded values)
__device__ float g_attn[ROWS * DM];        // [8192, 1024]  (tf32-rounded values)
__device__ float g_xr[ROWS * DM];          // rounded x
__device__ float g_wqkvT[QKV_N * DM];      // rounded w_qkv^T  [3072,1024]
__device__ float g_wprojT[DM * DM];        // rounded w_proj^T [1024,1024]

// ===========================================================================
// helpers
// ===========================================================================
__device__ __forceinline__ uint32_t smem_u32(const void* p) {
    uint32_t a;
    asm("{ .reg .u64 t; cvta.to.shared.u64 t, %1; cvt.u32.u64 %0, t; }"
        : "=r"(a) : "l"(p));
    return a;
}
__device__ __forceinline__ uint32_t f2tf32(float v) {
    uint32_t u;
    asm("cvt.rna.tf32.f32 %0, %1;" : "=r"(u) : "f"(v));
    return u;
}
__device__ __forceinline__ float roundtf(float v) {
    return __uint_as_float(f2tf32(v));
}
// single-MUFU exp2
__device__ __forceinline__ float ex2(float v) {
    float r;
    asm("ex2.approx.ftz.f32 %0, %1;" : "=f"(r) : "f"(v));
    return r;
}
__device__ __forceinline__ uint32_t lds1(uint32_t a) {
    uint32_t v;
    asm volatile("ld.shared.b32 %0, [%1];" : "=r"(v) : "r"(a));
    return v;
}
__device__ __forceinline__ void mma_tf32(float* d, const uint32_t* a, const uint32_t* b) {
    asm volatile(
        "mma.sync.aligned.m16n8k8.row.col.f32.tf32.tf32.f32 "
        "{%0,%1,%2,%3}, {%4,%5,%6,%7}, {%8,%9}, {%0,%1,%2,%3};"
        : "+f"(d[0]), "+f"(d[1]), "+f"(d[2]), "+f"(d[3])
        : "r"(a[0]), "r"(a[1]), "r"(a[2]), "r"(a[3]), "r"(b[0]), "r"(b[1]));
}
__device__ __forceinline__ void cp_async16(uint32_t dst, const void* src) {
    asm volatile("cp.async.cg.shared.global [%0], [%1], 16;"
                 :: "r"(dst), "l"(src) : "memory");
}
#define CP_COMMIT() asm volatile("cp.async.commit_group;" ::: "memory")
#define CP_WAIT1()  asm volatile("cp.async.wait_group 1;" ::: "memory")

// ===========================================================================
// Pre-pass kernels
// ===========================================================================
__global__ __launch_bounds__(256) void round4_kernel(
    const float* __restrict__ in, float* __restrict__ out, int n4)
{
    int i = blockIdx.x * 256 + threadIdx.x;
    if (i < n4) {
        float4 v = ((const float4*)in)[i];
        v.x = roundtf(v.x); v.y = roundtf(v.y);
        v.z = roundtf(v.z); v.w = roundtf(v.w);
        ((float4*)out)[i] = v;
    }
}

__global__ __launch_bounds__(256) void transpose_round_kernel(
    const float* __restrict__ in, float* __restrict__ out, int R, int C)
{
    __shared__ float t[32][33];
    int cx = blockIdx.x * 32;
    int ry = blockIdx.y * 32;
#pragma unroll
    for (int i = 0; i < 32; i += 8)
        t[threadIdx.y + i][threadIdx.x] =
            in[(size_t)(ry + threadIdx.y + i) * C + cx + threadIdx.x];
    __syncthreads();
#pragma unroll
    for (int i = 0; i < 32; i += 8)
        out[(size_t)(cx + threadIdx.y + i) * R + ry + threadIdx.x] =
            roundtf(t[threadIdx.x][threadIdx.y + i]);
}

// ===========================================================================
// GEMM (NT): unchanged from R7/R9 (validated at 300us / 172 TF/s).
// ===========================================================================
#define GEMM_SMEM (3 * 32768)

template<bool ROUND_OUT>
__global__ __launch_bounds__(256, 2) void gemm_cp_kernel(
    const float* __restrict__ A, const float* __restrict__ BT,
    float* __restrict__ C, int N, int K)
{
    extern __shared__ float gs[];
    const int tid  = threadIdx.x;
    const int lane = tid & 31;
    const int wid  = tid >> 5;
    const int wm   = wid >> 2;
    const int wn   = wid & 3;
    const int tig  = lane & 3;
    const int grp  = lane >> 2;
    const int bm = blockIdx.y * 128;
    const int bn = blockIdx.x * 128;
    const uint32_t sbase = smem_u32(gs);

    float acc[4][4][4];
#pragma unroll
    for (int i = 0; i < 4; ++i)
#pragma unroll
        for (int j = 0; j < 4; ++j)
#pragma unroll
            for (int r = 0; r < 4; ++r) acc[i][j][r] = 0.f;

    auto issue = [&](int c) {
        int s = c % 3;
        uint32_t abase = sbase + s * 32768;
        uint32_t bbase = abase + 16384;
        const float* Ap = A + (size_t)bm * K + c * 32;
        const float* Bp = BT + (size_t)bn * K + c * 32;
#pragma unroll
        for (int i = 0; i < 4; ++i) {
            int idx = tid + i * 256;
            int row = idx >> 3;
            int u   = idx & 7;
            uint32_t off = row * 128 + ((u ^ (row & 7)) * 16);
            cp_async16(abase + off, Ap + (size_t)row * K + u * 4);
            cp_async16(bbase + off, Bp + (size_t)row * K + u * 4);
        }
        CP_COMMIT();
    };

    const int NCH = K / 32;
    issue(0);
    issue(1);

    for (int c = 0; c < NCH; ++c) {
        CP_WAIT1();
        __syncthreads();
        if (c + 2 < NCH) issue(c + 2);

        const int s = c % 3;
        const uint32_t abase = sbase + s * 32768;
        const uint32_t bbase = abase + 16384;
#pragma unroll
        for (int g = 0; g < 4; ++g) {
            const uint32_t u0 = (uint32_t)(((2 * g)     ^ grp) * 16 + tig * 4);
            const uint32_t u1 = (uint32_t)(((2 * g + 1) ^ grp) * 16 + tig * 4);
            uint32_t af[4][4];
#pragma unroll
            for (int mt = 0; mt < 4; ++mt) {
                uint32_t rb = abase + (wm * 64 + mt * 16 + grp) * 128;
                af[mt][0] = lds1(rb + u0);
                af[mt][2] = lds1(rb + u1);
                af[mt][1] = lds1(rb + 1024 + u0);
                af[mt][3] = lds1(rb + 1024 + u1);
            }
#pragma unroll
            for (int nt = 0; nt < 4; ++nt) {
                uint32_t nb = bbase + (wn * 32 + nt * 8 + grp) * 128;
                uint32_t bf[2];
                bf[0] = lds1(nb + u0);
                bf[1] = lds1(nb + u1);
#pragma unroll
                for (int mt = 0; mt < 4; ++mt)
                    mma_tf32(acc[mt][nt], af[mt], bf);
            }
        }
    }

#pragma unroll
    for (int mt = 0; mt < 4; ++mt) {
        int r = bm + wm * 64 + mt * 16 + grp;
#pragma unroll
        for (int nt = 0; nt < 4; ++nt) {
            int cc = bn + wn * 32 + nt * 8 + 2 * tig;
            float2 v0, v1;
            if (ROUND_OUT) {
                v0 = make_float2(roundtf(acc[mt][nt][0]), roundtf(acc[mt][nt][1]));
                v1 = make_float2(roundtf(acc[mt][nt][2]), roundtf(acc[mt][nt][3]));
            } else {
                v0 = make_float2(acc[mt][nt][0], acc[mt][nt][1]);
                v1 = make_float2(acc[mt][nt][2], acc[mt][nt][3]);
            }
            *(float2*)(C + (size_t)r * N + cc)       = v0;
            *(float2*)(C + (size_t)(r + 8) * N + cc) = v1;
        }
    }
}

// ===========================================================================
// Flash attention (tf32 mma.sync), 256 Q rows/CTA, 2 m-tiles per warp:
// every K/V B-fragment load feeds TWO mmas (halves LDS per FLOP).
// Triple-buffered K/V, single barrier per tile, MUFU ex2 softmax.
// Grid: (T/256, B*NH). Block 256 (8 warps). Warp w owns Q rows [32w,32w+32).
// smem: Ps[256][68] (Q staging + P), Ks[3][64][68], Vs[3][64][68].
// ===========================================================================
#define FSTR 68
#define KVT  (64 * FSTR)
#define QTILE 256
#define FLASH_SMEM ((QTILE * FSTR + 6 * KVT) * 4)

__global__ __launch_bounds__(256) void flash_mma_kernel(
    const float* __restrict__ qkv, float* __restrict__ attn)
{
    extern __shared__ float sm[];
    float* Ps  = sm;                        // QTILE x FSTR
    float* KsA = sm + QTILE * FSTR;         // 3 x 64 x FSTR
    float* VsA = KsA + 3 * KVT;             // 3 x 64 x FSTR

    const int tid  = threadIdx.x;
    const int lane = tid & 31;
    const int wid  = tid >> 5;
    const int grp  = lane >> 2;
    const int tig  = lane & 3;
    const int qt = blockIdx.x;
    const int bh = blockIdx.y;
    const int b  = bh >> 4;
    const int h  = bh & 15;

    const int r0 = wid * 32 + grp;   // mt0 rows: r0, r0+8 ; mt1: r0+16, r0+24

    auto issue_kv = [&](int j) {
        int s = j % 3;
        float* Kd = KsA + s * KVT;
        float* Vd = VsA + s * KVT;
        const size_t kbase = (size_t)(b * T_ + j * 64) * QKV_N + h * DH;
#pragma unroll
        for (int i = 0; i < 4; ++i) {
            int idx = tid + i * 256;
            int row = idx >> 4;
            int c4  = idx & 15;
            const float* gk = qkv + kbase + (size_t)row * QKV_N + c4 * 4 + DM;
            cp_async16(smem_u32(&Kd[row * FSTR + c4 * 4]), gk);
            cp_async16(smem_u32(&Vd[row * FSTR + c4 * 4]), gk + DM);
        }
        CP_COMMIT();
    };

    issue_kv(0);
    issue_kv(1);

    // ---- stage Q tile (x 0.125*log2e; values already tf32) ----
    const float QSCALE = 0.125f * 1.4426950408889634f;
    const size_t qbase = (size_t)(b * T_ + qt * QTILE) * QKV_N + h * DH;
#pragma unroll
    for (int i = 0; i < 16; ++i) {
        int idx = tid + i * 256;               // 4096 float4 slots
        int row = idx >> 4;
        int c4  = idx & 15;
        float4 v = *(const float4*)&qkv[qbase + (size_t)row * QKV_N + c4 * 4];
        float* p = &Ps[row * FSTR + c4 * 4];
        p[0] = roundtf(v.x * QSCALE);
        p[1] = roundtf(v.y * QSCALE);
        p[2] = roundtf(v.z * QSCALE);
        p[3] = roundtf(v.w * QSCALE);
    }
    __syncthreads();

    // ---- Q fragments into registers (2 m-tiles) ----
    uint32_t qf[2][8][4];
#pragma unroll
    for (int m = 0; m < 2; ++m) {
        int rr = r0 + 16 * m;
#pragma unroll
        for (int kc = 0; kc < 8; ++kc) {
            qf[m][kc][0] = __float_as_uint(Ps[rr * FSTR + 8 * kc + tig]);
            qf[m][kc][1] = __float_as_uint(Ps[(rr + 8) * FSTR + 8 * kc + tig]);
            qf[m][kc][2] = __float_as_uint(Ps[rr * FSTR + 8 * kc + tig + 4]);
            qf[m][kc][3] = __float_as_uint(Ps[(rr + 8) * FSTR + 8 * kc + tig + 4]);
        }
    }

    float Oa[2][8][4];
#pragma unroll
    for (int m = 0; m < 2; ++m)
#pragma unroll
        for (int nt = 0; nt < 8; ++nt)
#pragma unroll
            for (int r = 0; r < 4; ++r) Oa[m][nt][r] = 0.f;
    float mrun[2][2] = {{-INFINITY, -INFINITY}, {-INFINITY, -INFINITY}};
    float lrun[2][2] = {{0.f, 0.f}, {0.f, 0.f}};

    const int NT = T_ / 64;
    for (int j = 0; j < NT; ++j) {
        CP_WAIT1();
        __syncthreads();             // tile j resident; prev iter fully consumed
        if (j + 2 < NT) issue_kv(j + 2);

        const float* Kb = KsA + (j % 3) * KVT;
        const float* Vb = VsA + (j % 3) * KVT;

        // ---- S = Q @ K^T : each bf feeds 2 mmas ----
        float Sa[2][8][4];
#pragma unroll
        for (int m = 0; m < 2; ++m)
#pragma unroll
            for (int nt = 0; nt < 8; ++nt)
#pragma unroll
                for (int r = 0; r < 4; ++r) Sa[m][nt][r] = 0.f;
#pragma unroll
        for (int kc = 0; kc < 8; ++kc) {
#pragma unroll
            for (int nt = 0; nt < 8; ++nt) {
                uint32_t bf[2];
                bf[0] = __float_as_uint(Kb[(8 * nt + grp) * FSTR + 8 * kc + tig]);
                bf[1] = __float_as_uint(Kb[(8 * nt + grp) * FSTR + 8 * kc + tig + 4]);
                mma_tf32(Sa[0][nt], qf[0][kc], bf);
                mma_tf32(Sa[1][nt], qf[1][kc], bf);
            }
        }

        // ---- online softmax per m-tile (MUFU ex2) ----
#pragma unroll
        for (int m = 0; m < 2; ++m) {
            int rr = r0 + 16 * m;
            float ml0 = -INFINITY, ml1 = -INFINITY;
#pragma unroll
            for (int nt = 0; nt < 8; ++nt) {
                ml0 = fmaxf(ml0, fmaxf(Sa[m][nt][0], Sa[m][nt][1]));
                ml1 = fmaxf(ml1, fmaxf(Sa[m][nt][2], Sa[m][nt][3]));
            }
            ml0 = fmaxf(ml0, __shfl_xor_sync(0xffffffffu, ml0, 1));
            ml0 = fmaxf(ml0, __shfl_xor_sync(0xffffffffu, ml0, 2));
            ml1 = fmaxf(ml1, __shfl_xor_sync(0xffffffffu, ml1, 1));
            ml1 = fmaxf(ml1, __shfl_xor_sync(0xffffffffu, ml1, 2));

            float mnew0 = fmaxf(mrun[m][0], ml0);
            float mnew1 = fmaxf(mrun[m][1], ml1);
            float corr0 = ex2(mrun[m][0] - mnew0);
            float corr1 = ex2(mrun[m][1] - mnew1);

            float ls0 = 0.f, ls1 = 0.f;
#pragma unroll
            for (int nt = 0; nt < 8; ++nt) {
                float p00 = ex2(Sa[m][nt][0] - mnew0);
                float p01 = ex2(Sa[m][nt][1] - mnew0);
                float p10 = ex2(Sa[m][nt][2] - mnew1);
                float p11 = ex2(Sa[m][nt][3] - mnew1);
                ls0 += p00 + p01;
                ls1 += p10 + p11;
                float2 w0, w1;
                w0.x = __uint_as_float(f2tf32(p00));
                w0.y = __uint_as_float(f2tf32(p01));
                w1.x = __uint_as_float(f2tf32(p10));
                w1.y = __uint_as_float(f2tf32(p11));
                *(float2*)&Ps[rr * FSTR + 8 * nt + 2 * tig]       = w0;
                *(float2*)&Ps[(rr + 8) * FSTR + 8 * nt + 2 * tig] = w1;
            }
            ls0 += __shfl_xor_sync(0xffffffffu, ls0, 1);
            ls0 += __shfl_xor_sync(0xffffffffu, ls0, 2);
            ls1 += __shfl_xor_sync(0xffffffffu, ls1, 1);
            ls1 += __shfl_xor_sync(0xffffffffu, ls1, 2);

            lrun[m][0] = lrun[m][0] * corr0 + ls0;
            lrun[m][1] = lrun[m][1] * corr1 + ls1;
            mrun[m][0] = mnew0;
            mrun[m][1] = mnew1;
#pragma unroll
            for (int nt = 0; nt < 8; ++nt) {
                Oa[m][nt][0] *= corr0;
                Oa[m][nt][1] *= corr0;
                Oa[m][nt][2] *= corr1;
                Oa[m][nt][3] *= corr1;
            }
        }
        __syncwarp();

        // ---- O += P @ V : each bf feeds 2 mmas ----
#pragma unroll
        for (int kc = 0; kc < 8; ++kc) {
            uint32_t af[2][4];
#pragma unroll
            for (int m = 0; m < 2; ++m) {
                int rr = r0 + 16 * m;
                af[m][0] = __float_as_uint(Ps[rr * FSTR + 8 * kc + tig]);
                af[m][1] = __float_as_uint(Ps[(rr + 8) * FSTR + 8 * kc + tig]);
                af[m][2] = __float_as_uint(Ps[rr * FSTR + 8 * kc + tig + 4]);
                af[m][3] = __float_as_uint(Ps[(rr + 8) * FSTR + 8 * kc + tig + 4]);
            }
#pragma unroll
            for (int nt = 0; nt < 8; ++nt) {
                uint32_t bf[2];
                bf[0] = __float_as_uint(Vb[(8 * kc + tig) * FSTR + 8 * nt + grp]);
                bf[1] = __float_as_uint(Vb[(8 * kc + tig + 4) * FSTR + 8 * nt + grp]);
                mma_tf32(Oa[0][nt], af[0], bf);
                mma_tf32(Oa[1][nt], af[1], bf);
            }
        }
        // no bottom barrier (triple buffer + top barrier)
    }

    // ---- epilogue ----
#pragma unroll
    for (int m = 0; m < 2; ++m) {
        int rr = r0 + 16 * m;
        const float inv0 = 1.f / lrun[m][0];
        const float inv1 = 1.f / lrun[m][1];
        float* o0 = attn + (size_t)(b * T_ + qt * QTILE + rr) * DM + h * DH;
        float* o1 = attn + (size_t)(b * T_ + qt * QTILE + rr + 8) * DM + h * DH;
#pragma unroll
        for (int nt = 0; nt < 8; ++nt) {
            float2 v0 = make_float2(roundtf(Oa[m][nt][0] * inv0),
                                    roundtf(Oa[m][nt][1] * inv0));
            float2 v1 = make_float2(roundtf(Oa[m][nt][2] * inv1),
                                    roundtf(Oa[m][nt][3] * inv1));
            *(float2*)(o0 + 8 * nt + 2 * tig) = v0;
            *(float2*)(o1 + 8 * nt + 2 * tig) = v1;
        }
    }
}

// ---------------------------------------------------------------------------
extern "C" void kernel_launch(void* const* d_in, const int* in_sizes, int n_in,
                              void* d_out, int out_size)
{
    const float* x      = (const float*)d_in[0];   // [4,2048,1024]
    const float* w_qkv  = (const float*)d_in[1];   // [1024,3072]
    const float* w_proj = (const float*)d_in[2];   // [1024,1024]
    float* out = (float*)d_out;                    // [4,2048,1024]

    float *qkvbuf, *attnbuf, *xr, *wqkvT, *wprojT;
    cudaGetSymbolAddress((void**)&qkvbuf, g_qkv);
    cudaGetSymbolAddress((void**)&attnbuf, g_attn);
    cudaGetSymbolAddress((void**)&xr, g_xr);
    cudaGetSymbolAddress((void**)&wqkvT, g_wqkvT);
    cudaGetSymbolAddress((void**)&wprojT, g_wprojT);

    static bool attr_set = false;
    if (!attr_set) {
        cudaFuncSetAttribute(flash_mma_kernel,
                             cudaFuncAttributeMaxDynamicSharedMemorySize,
                             FLASH_SMEM);
        cudaFuncSetAttribute(gemm_cp_kernel<true>,
                             cudaFuncAttributeMaxDynamicSharedMemorySize,
                             GEMM_SMEM);
        cudaFuncSetAttribute(gemm_cp_kernel<false>,
                             cudaFuncAttributeMaxDynamicSharedMemorySize,
                             GEMM_SMEM);
        attr_set = true;
    }

    // 0) Pre-pass: round x; transpose+round weights.
    {
        int n4 = ROWS * DM / 4;
        round4_kernel<<<(n4 + 255) / 256, 256>>>(x, xr, n4);
        dim3 tb(32, 8);
        transpose_round_kernel<<<dim3(QKV_N / 32, DM / 32), tb>>>(w_qkv, wqkvT, DM, QKV_N);
        transpose_round_kernel<<<dim3(DM / 32, DM / 32), tb>>>(w_proj, wprojT, DM, DM);
    }

    // 1) QKV projection: [8192,1024] @ [1024,3072] -> rounded qkv
    {
        dim3 grid(QKV_N / 128, ROWS / 128);
        gemm_cp_kernel<true><<<grid, 256, GEMM_SMEM>>>(xr, wqkvT, qkvbuf, QKV_N, DM);
    }

    // 2) Attention -> rounded attn
    {
        dim3 grid(T_ / QTILE, B_ * NH);
        flash_mma_kernel<<<grid, 256, FLASH_SMEM>>>(qkvbuf, attnbuf);
    }

    // 3) Output projection: [8192,1024] @ [1024,1024] -> fp32 out
    {
        dim3 grid(DM / 128, ROWS / 128);
        gemm_cp_kernel<false><<<grid, 256, GEMM_SMEM>>>(attnbuf, wprojT, out, DM, DM);
    }
}

// round 11
// speedup vs baseline: 1.8127x; 1.0440x over previous
#include <cuda_runtime.h>
#include <cuda_bf16.h>
#include <math.h>
#include <cstdint>

// Problem constants
#define B_    4
#define T_    2048
#define DM    1024
#define NH    16
#define DH    64
#define ROWS  (B_ * T_)          // 8192
#define QKV_N (3 * DM)           // 3072

// Scratch (device globals: allocation-free)
__device__ float g_qkv[ROWS * QKV_N];      // [8192, 3072]  (tf32-rounded values)
__device__ float g_attn[ROWS * DM];        // [8192, 1024]  (tf32-rounded values)
__device__ float g_xr[ROWS * DM];          // rounded x
__device__ float g_wqkvT[QKV_N * DM];      // rounded w_qkv^T  [3072,1024]
__device__ float g_wprojT[DM * DM];        // rounded w_proj^T [1024,1024]

// ===========================================================================
// helpers
// ===========================================================================
__device__ __forceinline__ uint32_t smem_u32(const void* p) {
    uint32_t a;
    asm("{ .reg .u64 t; cvta.to.shared.u64 t, %1; cvt.u32.u64 %0, t; }"
        : "=r"(a) : "l"(p));
    return a;
}
__device__ __forceinline__ uint32_t f2tf32(float v) {
    uint32_t u;
    asm("cvt.rna.tf32.f32 %0, %1;" : "=r"(u) : "f"(v));
    return u;
}
__device__ __forceinline__ float roundtf(float v) {
    return __uint_as_float(f2tf32(v));
}
// single-MUFU exp2
__device__ __forceinline__ float ex2(float v) {
    float r;
    asm("ex2.approx.ftz.f32 %0, %1;" : "=f"(r) : "f"(v));
    return r;
}
__device__ __forceinline__ uint32_t lds1(uint32_t a) {
    uint32_t v;
    asm volatile("ld.shared.b32 %0, [%1];" : "=r"(v) : "r"(a));
    return v;
}
__device__ __forceinline__ void mma_tf32(float* d, const uint32_t* a, const uint32_t* b) {
    asm volatile(
        "mma.sync.aligned.m16n8k8.row.col.f32.tf32.tf32.f32 "
        "{%0,%1,%2,%3}, {%4,%5,%6,%7}, {%8,%9}, {%0,%1,%2,%3};"
        : "+f"(d[0]), "+f"(d[1]), "+f"(d[2]), "+f"(d[3])
        : "r"(a[0]), "r"(a[1]), "r"(a[2]), "r"(a[3]), "r"(b[0]), "r"(b[1]));
}
__device__ __forceinline__ void cp_async16(uint32_t dst, const void* src) {
    asm volatile("cp.async.cg.shared.global [%0], [%1], 16;"
                 :: "r"(dst), "l"(src) : "memory");
}
#define CP_COMMIT() asm volatile("cp.async.commit_group;" ::: "memory")
#define CP_WAIT1()  asm volatile("cp.async.wait_group 1;" ::: "memory")

// ===========================================================================
// Pre-pass kernels
// ===========================================================================
__global__ __launch_bounds__(256) void round4_kernel(
    const float* __restrict__ in, float* __restrict__ out, int n4)
{
    int i = blockIdx.x * 256 + threadIdx.x;
    if (i < n4) {
        float4 v = ((const float4*)in)[i];
        v.x = roundtf(v.x); v.y = roundtf(v.y);
        v.z = roundtf(v.z); v.w = roundtf(v.w);
        ((float4*)out)[i] = v;
    }
}

__global__ __launch_bounds__(256) void transpose_round_kernel(
    const float* __restrict__ in, float* __restrict__ out, int R, int C)
{
    __shared__ float t[32][33];
    int cx = blockIdx.x * 32;
    int ry = blockIdx.y * 32;
#pragma unroll
    for (int i = 0; i < 32; i += 8)
        t[threadIdx.y + i][threadIdx.x] =
            in[(size_t)(ry + threadIdx.y + i) * C + cx + threadIdx.x];
    __syncthreads();
#pragma unroll
    for (int i = 0; i < 32; i += 8)
        out[(size_t)(cx + threadIdx.y + i) * R + ry + threadIdx.x] =
            roundtf(t[threadIdx.x][threadIdx.y + i]);
}

// ===========================================================================
// GEMM (NT): unchanged (validated 300us / 172 TF/s).
// ===========================================================================
#define GEMM_SMEM (3 * 32768)

template<bool ROUND_OUT>
__global__ __launch_bounds__(256, 2) void gemm_cp_kernel(
    const float* __restrict__ A, const float* __restrict__ BT,
    float* __restrict__ C, int N, int K)
{
    extern __shared__ float gs[];
    const int tid  = threadIdx.x;
    const int lane = tid & 31;
    const int wid  = tid >> 5;
    const int wm   = wid >> 2;
    const int wn   = wid & 3;
    const int tig  = lane & 3;
    const int grp  = lane >> 2;
    const int bm = blockIdx.y * 128;
    const int bn = blockIdx.x * 128;
    const uint32_t sbase = smem_u32(gs);

    float acc[4][4][4];
#pragma unroll
    for (int i = 0; i < 4; ++i)
#pragma unroll
        for (int j = 0; j < 4; ++j)
#pragma unroll
            for (int r = 0; r < 4; ++r) acc[i][j][r] = 0.f;

    auto issue = [&](int c) {
        int s = c % 3;
        uint32_t abase = sbase + s * 32768;
        uint32_t bbase = abase + 16384;
        const float* Ap = A + (size_t)bm * K + c * 32;
        const float* Bp = BT + (size_t)bn * K + c * 32;
#pragma unroll
        for (int i = 0; i < 4; ++i) {
            int idx = tid + i * 256;
            int row = idx >> 3;
            int u   = idx & 7;
            uint32_t off = row * 128 + ((u ^ (row & 7)) * 16);
            cp_async16(abase + off, Ap + (size_t)row * K + u * 4);
            cp_async16(bbase + off, Bp + (size_t)row * K + u * 4);
        }
        CP_COMMIT();
    };

    const int NCH = K / 32;
    issue(0);
    issue(1);

    for (int c = 0; c < NCH; ++c) {
        CP_WAIT1();
        __syncthreads();
        if (c + 2 < NCH) issue(c + 2);

        const int s = c % 3;
        const uint32_t abase = sbase + s * 32768;
        const uint32_t bbase = abase + 16384;
#pragma unroll
        for (int g = 0; g < 4; ++g) {
            const uint32_t u0 = (uint32_t)(((2 * g)     ^ grp) * 16 + tig * 4);
            const uint32_t u1 = (uint32_t)(((2 * g + 1) ^ grp) * 16 + tig * 4);
            uint32_t af[4][4];
#pragma unroll
            for (int mt = 0; mt < 4; ++mt) {
                uint32_t rb = abase + (wm * 64 + mt * 16 + grp) * 128;
                af[mt][0] = lds1(rb + u0);
                af[mt][2] = lds1(rb + u1);
                af[mt][1] = lds1(rb + 1024 + u0);
                af[mt][3] = lds1(rb + 1024 + u1);
            }
#pragma unroll
            for (int nt = 0; nt < 4; ++nt) {
                uint32_t nb = bbase + (wn * 32 + nt * 8 + grp) * 128;
                uint32_t bf[2];
                bf[0] = lds1(nb + u0);
                bf[1] = lds1(nb + u1);
#pragma unroll
                for (int mt = 0; mt < 4; ++mt)
                    mma_tf32(acc[mt][nt], af[mt], bf);
            }
        }
    }

#pragma unroll
    for (int mt = 0; mt < 4; ++mt) {
        int r = bm + wm * 64 + mt * 16 + grp;
#pragma unroll
        for (int nt = 0; nt < 4; ++nt) {
            int cc = bn + wn * 32 + nt * 8 + 2 * tig;
            float2 v0, v1;
            if (ROUND_OUT) {
                v0 = make_float2(roundtf(acc[mt][nt][0]), roundtf(acc[mt][nt][1]));
                v1 = make_float2(roundtf(acc[mt][nt][2]), roundtf(acc[mt][nt][3]));
            } else {
                v0 = make_float2(acc[mt][nt][0], acc[mt][nt][1]);
                v1 = make_float2(acc[mt][nt][2], acc[mt][nt][3]);
            }
            *(float2*)(C + (size_t)r * N + cc)       = v0;
            *(float2*)(C + (size_t)(r + 8) * N + cc) = v1;
        }
    }
}

// ===========================================================================
// Flash attention (tf32 mma.sync), 256 Q rows/CTA, 2 m-tiles/warp.
// NEW: cross-tile PV deferral (PV of tile j-1 issued right after S of tile j,
// so the tensor queue stays full while softmax's MUFU chains run) + 4-deep
// K/V ring + V stored at stride 72 (conflict-free PV B-fragments).
// Grid: (T/256, B*NH). Block 256 (8 warps). Warp w owns Q rows [32w,32w+32).
// ===========================================================================
#define FSTR  68          // Ps / Ks stride
#define FSTRV 72          // Vs stride (8*tig+grp spans all 32 banks)
#define KVTK (64 * FSTR)
#define KVTV (64 * FSTRV)
#define NBUF 4
#define QTILE 256
#define FLASH_SMEM ((QTILE * FSTR + NBUF * KVTK + NBUF * KVTV) * 4)

__global__ __launch_bounds__(256) void flash_mma_kernel(
    const float* __restrict__ qkv, float* __restrict__ attn)
{
    extern __shared__ float sm[];
    float* Ps  = sm;                        // QTILE x FSTR
    float* KsA = sm + QTILE * FSTR;         // NBUF x 64 x FSTR
    float* VsA = KsA + NBUF * KVTK;         // NBUF x 64 x FSTRV

    const int tid  = threadIdx.x;
    const int lane = tid & 31;
    const int wid  = tid >> 5;
    const int grp  = lane >> 2;
    const int tig  = lane & 3;
    const int qt = blockIdx.x;
    const int bh = blockIdx.y;
    const int b  = bh >> 4;
    const int h  = bh & 15;

    const int r0 = wid * 32 + grp;   // mt0 rows: r0, r0+8 ; mt1: r0+16, r0+24

    auto issue_kv = [&](int j) {
        int s = j & (NBUF - 1);
        float* Kd = KsA + s * KVTK;
        float* Vd = VsA + s * KVTV;
        const size_t kbase = (size_t)(b * T_ + j * 64) * QKV_N + h * DH;
#pragma unroll
        for (int i = 0; i < 4; ++i) {
            int idx = tid + i * 256;
            int row = idx >> 4;
            int c4  = idx & 15;
            const float* gk = qkv + kbase + (size_t)row * QKV_N + c4 * 4 + DM;
            cp_async16(smem_u32(&Kd[row * FSTR + c4 * 4]), gk);
            cp_async16(smem_u32(&Vd[row * FSTRV + c4 * 4]), gk + DM);
        }
        CP_COMMIT();
    };

    issue_kv(0);
    issue_kv(1);

    // ---- stage Q tile (x 0.125*log2e; values already tf32) ----
    const float QSCALE = 0.125f * 1.4426950408889634f;
    const size_t qbase = (size_t)(b * T_ + qt * QTILE) * QKV_N + h * DH;
#pragma unroll
    for (int i = 0; i < 16; ++i) {
        int idx = tid + i * 256;
        int row = idx >> 4;
        int c4  = idx & 15;
        float4 v = *(const float4*)&qkv[qbase + (size_t)row * QKV_N + c4 * 4];
        float* p = &Ps[row * FSTR + c4 * 4];
        p[0] = roundtf(v.x * QSCALE);
        p[1] = roundtf(v.y * QSCALE);
        p[2] = roundtf(v.z * QSCALE);
        p[3] = roundtf(v.w * QSCALE);
    }
    __syncthreads();

    // ---- Q fragments into registers (2 m-tiles) ----
    uint32_t qf[2][8][4];
#pragma unroll
    for (int m = 0; m < 2; ++m) {
        int rr = r0 + 16 * m;
#pragma unroll
        for (int kc = 0; kc < 8; ++kc) {
            qf[m][kc][0] = __float_as_uint(Ps[rr * FSTR + 8 * kc + tig]);
            qf[m][kc][1] = __float_as_uint(Ps[(rr + 8) * FSTR + 8 * kc + tig]);
            qf[m][kc][2] = __float_as_uint(Ps[rr * FSTR + 8 * kc + tig + 4]);
            qf[m][kc][3] = __float_as_uint(Ps[(rr + 8) * FSTR + 8 * kc + tig + 4]);
        }
    }

    float Oa[2][8][4];
#pragma unroll
    for (int m = 0; m < 2; ++m)
#pragma unroll
        for (int nt = 0; nt < 8; ++nt)
#pragma unroll
            for (int r = 0; r < 4; ++r) Oa[m][nt][r] = 0.f;
    float mrun[2][2] = {{-INFINITY, -INFINITY}, {-INFINITY, -INFINITY}};
    float lrun[2][2] = {{0.f, 0.f}, {0.f, 0.f}};

    // deferred-PV: accumulate P(j-1) @ V(j-1) into Oa (both m share bf)
    auto pv = [&](const float* Vb_) {
#pragma unroll
        for (int kc = 0; kc < 8; ++kc) {
            uint32_t af[2][4];
#pragma unroll
            for (int m = 0; m < 2; ++m) {
                int rr = r0 + 16 * m;
                af[m][0] = __float_as_uint(Ps[rr * FSTR + 8 * kc + tig]);
                af[m][1] = __float_as_uint(Ps[(rr + 8) * FSTR + 8 * kc + tig]);
                af[m][2] = __float_as_uint(Ps[rr * FSTR + 8 * kc + tig + 4]);
                af[m][3] = __float_as_uint(Ps[(rr + 8) * FSTR + 8 * kc + tig + 4]);
            }
#pragma unroll
            for (int nt = 0; nt < 8; ++nt) {
                uint32_t bf[2];
                bf[0] = __float_as_uint(Vb_[(8 * kc + tig) * FSTRV + 8 * nt + grp]);
                bf[1] = __float_as_uint(Vb_[(8 * kc + tig + 4) * FSTRV + 8 * nt + grp]);
                mma_tf32(Oa[0][nt], af[0], bf);
                mma_tf32(Oa[1][nt], af[1], bf);
            }
        }
    };

    const float* Vprev = VsA;
    const int NT = T_ / 64;
    for (int j = 0; j < NT; ++j) {
        CP_WAIT1();
        __syncthreads();             // tile j resident; iter j-1 fully consumed
        if (j + 2 < NT) issue_kv(j + 2);

        const float* Kb = KsA + (j & (NBUF - 1)) * KVTK;
        const float* Vb = VsA + (j & (NBUF - 1)) * KVTV;

        // ---- S = Q @ K^T (both m, shared bf) ----
        float Sa[2][8][4];
#pragma unroll
        for (int m = 0; m < 2; ++m)
#pragma unroll
            for (int nt = 0; nt < 8; ++nt)
#pragma unroll
                for (int r = 0; r < 4; ++r) Sa[m][nt][r] = 0.f;
#pragma unroll
        for (int kc = 0; kc < 8; ++kc) {
#pragma unroll
            for (int nt = 0; nt < 8; ++nt) {
                uint32_t bf[2];
                bf[0] = __float_as_uint(Kb[(8 * nt + grp) * FSTR + 8 * kc + tig]);
                bf[1] = __float_as_uint(Kb[(8 * nt + grp) * FSTR + 8 * kc + tig + 4]);
                mma_tf32(Sa[0][nt], qf[0][kc], bf);
                mma_tf32(Sa[1][nt], qf[1][kc], bf);
            }
        }

        // ---- deferred PV of previous tile: keeps tensor queue full
        //      while the softmax below runs its MUFU/shfl chains ----
        if (j > 0) pv(Vprev);

        // ---- online softmax per m-tile (MUFU ex2), writes P(j) ----
#pragma unroll
        for (int m = 0; m < 2; ++m) {
            int rr = r0 + 16 * m;
            float ml0 = -INFINITY, ml1 = -INFINITY;
#pragma unroll
            for (int nt = 0; nt < 8; ++nt) {
                ml0 = fmaxf(ml0, fmaxf(Sa[m][nt][0], Sa[m][nt][1]));
                ml1 = fmaxf(ml1, fmaxf(Sa[m][nt][2], Sa[m][nt][3]));
            }
            ml0 = fmaxf(ml0, __shfl_xor_sync(0xffffffffu, ml0, 1));
            ml0 = fmaxf(ml0, __shfl_xor_sync(0xffffffffu, ml0, 2));
            ml1 = fmaxf(ml1, __shfl_xor_sync(0xffffffffu, ml1, 1));
            ml1 = fmaxf(ml1, __shfl_xor_sync(0xffffffffu, ml1, 2));

            float mnew0 = fmaxf(mrun[m][0], ml0);
            float mnew1 = fmaxf(mrun[m][1], ml1);
            float corr0 = ex2(mrun[m][0] - mnew0);
            float corr1 = ex2(mrun[m][1] - mnew1);

            float ls0 = 0.f, ls1 = 0.f;
#pragma unroll
            for (int nt = 0; nt < 8; ++nt) {
                float p00 = ex2(Sa[m][nt][0] - mnew0);
                float p01 = ex2(Sa[m][nt][1] - mnew0);
                float p10 = ex2(Sa[m][nt][2] - mnew1);
                float p11 = ex2(Sa[m][nt][3] - mnew1);
                ls0 += p00 + p01;
                ls1 += p10 + p11;
                float2 w0, w1;
                w0.x = __uint_as_float(f2tf32(p00));
                w0.y = __uint_as_float(f2tf32(p01));
                w1.x = __uint_as_float(f2tf32(p10));
                w1.y = __uint_as_float(f2tf32(p11));
                *(float2*)&Ps[rr * FSTR + 8 * nt + 2 * tig]       = w0;
                *(float2*)&Ps[(rr + 8) * FSTR + 8 * nt + 2 * tig] = w1;
            }
            ls0 += __shfl_xor_sync(0xffffffffu, ls0, 1);
            ls0 += __shfl_xor_sync(0xffffffffu, ls0, 2);
            ls1 += __shfl_xor_sync(0xffffffffu, ls1, 1);
            ls1 += __shfl_xor_sync(0xffffffffu, ls1, 2);

            lrun[m][0] = lrun[m][0] * corr0 + ls0;
            lrun[m][1] = lrun[m][1] * corr1 + ls1;
            mrun[m][0] = mnew0;
            mrun[m][1] = mnew1;
#pragma unroll
            for (int nt = 0; nt < 8; ++nt) {
                Oa[m][nt][0] *= corr0;
                Oa[m][nt][1] *= corr0;
                Oa[m][nt][2] *= corr1;
                Oa[m][nt][3] *= corr1;
            }
        }
        __syncwarp();                // P(j) visible to all lanes for next pv
        Vprev = Vb;
    }

    // tail: PV of the last tile
    pv(Vprev);

    // ---- epilogue ----
#pragma unroll
    for (int m = 0; m < 2; ++m) {
        int rr = r0 + 16 * m;
        const float inv0 = 1.f / lrun[m][0];
        const float inv1 = 1.f / lrun[m][1];
        float* o0 = attn + (size_t)(b * T_ + qt * QTILE + rr) * DM + h * DH;
        float* o1 = attn + (size_t)(b * T_ + qt * QTILE + rr + 8) * DM + h * DH;
#pragma unroll
        for (int nt = 0; nt < 8; ++nt) {
            float2 v0 = make_float2(roundtf(Oa[m][nt][0] * inv0),
                                    roundtf(Oa[m][nt][1] * inv0));
            float2 v1 = make_float2(roundtf(Oa[m][nt][2] * inv1),
                                    roundtf(Oa[m][nt][3] * inv1));
            *(float2*)(o0 + 8 * nt + 2 * tig) = v0;
            *(float2*)(o1 + 8 * nt + 2 * tig) = v1;
        }
    }
}

// ---------------------------------------------------------------------------
extern "C" void kernel_launch(void* const* d_in, const int* in_sizes, int n_in,
                              void* d_out, int out_size)
{
    const float* x      = (const float*)d_in[0];   // [4,2048,1024]
    const float* w_qkv  = (const float*)d_in[1];   // [1024,3072]
    const float* w_proj = (const float*)d_in[2];   // [1024,1024]
    float* out = (float*)d_out;                    // [4,2048,1024]

    float *qkvbuf, *attnbuf, *xr, *wqkvT, *wprojT;
    cudaGetSymbolAddress((void**)&qkvbuf, g_qkv);
    cudaGetSymbolAddress((void**)&attnbuf, g_attn);
    cudaGetSymbolAddress((void**)&xr, g_xr);
    cudaGetSymbolAddress((void**)&wqkvT, g_wqkvT);
    cudaGetSymbolAddress((void**)&wprojT, g_wprojT);

    static bool attr_set = false;
    if (!attr_set) {
        cudaFuncSetAttribute(flash_mma_kernel,
                             cudaFuncAttributeMaxDynamicSharedMemorySize,
                             FLASH_SMEM);
        cudaFuncSetAttribute(gemm_cp_kernel<true>,
                             cudaFuncAttributeMaxDynamicSharedMemorySize,
                             GEMM_SMEM);
        cudaFuncSetAttribute(gemm_cp_kernel<false>,
                             cudaFuncAttributeMaxDynamicSharedMemorySize,
                             GEMM_SMEM);
        attr_set = true;
    }

    // 0) Pre-pass: round x; transpose+round weights.
    {
        int n4 = ROWS * DM / 4;
        round4_kernel<<<(n4 + 255) / 256, 256>>>(x, xr, n4);
        dim3 tb(32, 8);
        transpose_round_kernel<<<dim3(QKV_N / 32, DM / 32), tb>>>(w_qkv, wqkvT, DM, QKV_N);
        transpose_round_kernel<<<dim3(DM / 32, DM / 32), tb>>>(w_proj, wprojT, DM, DM);
    }

    // 1) QKV projection: [8192,1024] @ [1024,3072] -> rounded qkv
    {
        dim3 grid(QKV_N / 128, ROWS / 128);
        gemm_cp_kernel<true><<<grid, 256, GEMM_SMEM>>>(xr, wqkvT, qkvbuf, QKV_N, DM);
    }

    // 2) Attention -> rounded attn
    {
        dim3 grid(T_ / QTILE, B_ * NH);
        flash_mma_kernel<<<grid, 256, FLASH_SMEM>>>(qkvbuf, attnbuf);
    }

    // 3) Output projection: [8192,1024] @ [1024,1024] -> fp32 out
    {
        dim3 grid(DM / 128, ROWS / 128);
        gemm_cp_kernel<false><<<grid, 256, GEMM_SMEM>>>(attnbuf, wprojT, out, DM, DM);
    }
}